// round 6
// baseline (speedup 1.0000x reference)
#include <cuda_runtime.h>
#include <cuda_bf16.h>
#include <math.h>
#include <stdint.h>

#define NB   4
#define NS   2048
#define ND   1024
#define NH   16
#define NDH  64
#define MT   (NB*NS)          // 8192 rows
#define QKV_ELEMS ((size_t)NB*NH*NS*NDH)

// ---------------- scratch (device globals: no allocation allowed) ----------
__device__ float g_Q[QKV_ELEMS];              // fp32 pre-RoPE
__device__ float g_K[QKV_ELEMS];
__device__ __nv_bfloat16 g_Qh[QKV_ELEMS], g_Ql[QKV_ELEMS];   // post-RoPE, *0.125
__device__ __nv_bfloat16 g_Kh[QKV_ELEMS], g_Kl[QKV_ELEMS];
__device__ __nv_bfloat16 g_Vh[QKV_ELEMS], g_Vl[QKV_ELEMS];
__device__ __nv_bfloat16 g_xh[(size_t)MT*ND],   g_xl[(size_t)MT*ND];
__device__ __nv_bfloat16 g_wqh[(size_t)3*ND*ND], g_wql[(size_t)3*ND*ND];
__device__ __nv_bfloat16 g_woh[(size_t)ND*ND],  g_wol[(size_t)ND*ND];
__device__ __nv_bfloat16 g_ctxh[(size_t)MT*ND], g_ctxl[(size_t)MT*ND];

// ======================= helpers ===========================================
__device__ __forceinline__ uint32_t smem_u32(const void* p) {
    uint32_t a;
    asm("{ .reg .u64 t; cvta.to.shared.u64 t, %1; cvt.u32.u64 %0, t; }"
        : "=r"(a) : "l"(p));
    return a;
}
__device__ __forceinline__ void ldmx4(uint32_t addr, uint32_t r[4]) {
    asm volatile("ldmatrix.sync.aligned.m8n8.x4.shared.b16 {%0,%1,%2,%3}, [%4];"
                 : "=r"(r[0]), "=r"(r[1]), "=r"(r[2]), "=r"(r[3]) : "r"(addr));
}
__device__ __forceinline__ void ldmx4t(uint32_t addr, uint32_t r[4]) {
    asm volatile("ldmatrix.sync.aligned.m8n8.x4.trans.shared.b16 {%0,%1,%2,%3}, [%4];"
                 : "=r"(r[0]), "=r"(r[1]), "=r"(r[2]), "=r"(r[3]) : "r"(addr));
}
// NOT volatile: pure register op -> compiler may schedule/interleave freely
__device__ __forceinline__ void mma16816(float c[4], const uint32_t a[4],
                                         uint32_t b0, uint32_t b1) {
    asm("mma.sync.aligned.m16n8k16.row.col.f32.bf16.bf16.f32 "
        "{%0,%1,%2,%3}, {%4,%5,%6,%7}, {%8,%9}, {%0,%1,%2,%3};"
        : "+f"(c[0]), "+f"(c[1]), "+f"(c[2]), "+f"(c[3])
        : "r"(a[0]), "r"(a[1]), "r"(a[2]), "r"(a[3]), "r"(b0), "r"(b1));
}
__device__ __forceinline__ void split2(float x, float y, uint32_t& hi, uint32_t& lo) {
    __nv_bfloat162 h = __floats2bfloat162_rn(x, y);
    hi = *(uint32_t*)&h;
    __nv_bfloat162 l = __floats2bfloat162_rn(x - __bfloat162float(h.x),
                                             y - __bfloat162float(h.y));
    lo = *(uint32_t*)&l;
}
// XOR swizzle: 16B chunk c of 64B row
__device__ __forceinline__ uint32_t swz(int row, int c) {
    return (uint32_t)(row * 64 + ((c ^ ((row >> 1) & 3)) * 16));
}
// XOR swizzle for 128B rows
__device__ __forceinline__ uint32_t swz128(int row, int c) {
    return (uint32_t)(row * 128 + ((c ^ (row & 7)) * 16));
}
__device__ __forceinline__ void cpa16(uint32_t dst, const void* src) {
    asm volatile("cp.async.cg.shared.global [%0], [%1], 16;"
                 :: "r"(dst), "l"(src));
}
#define CP_COMMIT()  asm volatile("cp.async.commit_group;")
#define CP_WAIT(n)   asm volatile("cp.async.wait_group %0;" :: "n"(n))

// ===========================================================================
// split fp32 array into bf16 hi/lo
// ===========================================================================
__global__ void conv_split(const float4* __restrict__ in,
                           uint2* __restrict__ hi, uint2* __restrict__ lo, int n4)
{
    int i = blockIdx.x * blockDim.x + threadIdx.x;
    if (i >= n4) return;
    float4 v = in[i];
    uint32_t h0, l0, h1, l1;
    split2(v.x, v.y, h0, l0);
    split2(v.z, v.w, h1, l1);
    hi[i] = make_uint2(h0, h1);
    lo[i] = make_uint2(l0, l1);
}

// ===========================================================================
// bf16 3-term GEMM with pre-split operands + cp.async 4-stage pipeline.
// Term-major MMA ordering: accumulator reuse distance 4 (vs 2 before).
// ===========================================================================
#define GSTG 32768
#define GK_SMEM (4*GSTG)

template<int EPI>
__global__ __launch_bounds__(256, 1) void gemm_bf16(
    const __nv_bfloat16* __restrict__ Ah, const __nv_bfloat16* __restrict__ Al,
    const __nv_bfloat16* __restrict__ Wh, const __nv_bfloat16* __restrict__ Wl,
    const float* __restrict__ bias, float* __restrict__ C, int N, int K)
{
    extern __shared__ char smc[];
    const uint32_t sb = smem_u32(smc);

    const int tid  = threadIdx.x;
    const int warp = tid >> 5, lane = tid & 31;
    const int wm = warp & 3, cg = warp >> 2;
    const int m0 = blockIdx.y * 128, n0 = blockIdx.x * 128;

    const int rowA = tid >> 2, cA = tid & 3;
    const int rowB = (tid + 256) >> 2, cB = tid & 3;
    const uint32_t offA = swz(rowA, cA), offB = swz(rowB, cB);
    const __nv_bfloat16* pAhA = Ah + (size_t)(m0 + rowA) * K + cA * 8;
    const __nv_bfloat16* pAlA = Al + (size_t)(m0 + rowA) * K + cA * 8;
    const __nv_bfloat16* pWhA = Wh + (size_t)(n0 + rowA) * K + cA * 8;
    const __nv_bfloat16* pWlA = Wl + (size_t)(n0 + rowA) * K + cA * 8;
    const __nv_bfloat16* pAhB = Ah + (size_t)(m0 + rowB) * K + cB * 8;
    const __nv_bfloat16* pAlB = Al + (size_t)(m0 + rowB) * K + cB * 8;
    const __nv_bfloat16* pWhB = Wh + (size_t)(n0 + rowB) * K + cB * 8;
    const __nv_bfloat16* pWlB = Wl + (size_t)(n0 + rowB) * K + cB * 8;

    float acc[2][8][4];
    #pragma unroll
    for (int mt = 0; mt < 2; mt++)
        #pragma unroll
        for (int nt = 0; nt < 8; nt++)
            #pragma unroll
            for (int i = 0; i < 4; i++) acc[mt][nt][i] = 0.f;

    uint32_t aOff[2][2], bOff[2][4];
    #pragma unroll
    for (int h = 0; h < 2; h++) {
        #pragma unroll
        for (int mt = 0; mt < 2; mt++) {
            int r = wm * 32 + mt * 16 + (lane & 15);
            int c = h * 2 + ((lane >> 4) & 1);
            aOff[h][mt] = swz(r, c);
        }
        #pragma unroll
        for (int ntp = 0; ntp < 4; ntp++) {
            int r = cg * 64 + ntp * 16 + (lane & 7) + ((lane >> 4) & 1) * 8;
            int c = h * 2 + ((lane >> 3) & 1);
            bOff[h][ntp] = swz(r, c);
        }
    }

    const int NSTG = K / 32;

    auto issue = [&](int s) {
        const uint32_t base = sb + (s & 3) * GSTG;
        const int k0 = s * 32;
        cpa16(base + offA,         pAhA + k0);
        cpa16(base + 8192  + offA, pAlA + k0);
        cpa16(base + 16384 + offA, pWhA + k0);
        cpa16(base + 24576 + offA, pWlA + k0);
        cpa16(base + offB,         pAhB + k0);
        cpa16(base + 8192  + offB, pAlB + k0);
        cpa16(base + 16384 + offB, pWhB + k0);
        cpa16(base + 24576 + offB, pWlB + k0);
    };

    issue(0); CP_COMMIT();
    issue(1); CP_COMMIT();
    issue(2); CP_COMMIT();

    for (int s = 0; s < NSTG; s++) {
        CP_WAIT(2);
        __syncthreads();
        if (s + 3 < NSTG) issue(s + 3);
        CP_COMMIT();

        const uint32_t base = sb + (s & 3) * GSTG;
        #pragma unroll
        for (int h = 0; h < 2; h++) {
            uint32_t ah[2][4], al[2][4];
            #pragma unroll
            for (int mt = 0; mt < 2; mt++) {
                ldmx4(base + aOff[h][mt], ah[mt]);
                ldmx4(base + 8192 + aOff[h][mt], al[mt]);
            }
            #pragma unroll
            for (int ntp = 0; ntp < 4; ntp++) {
                uint32_t bh[4], bl[4];
                ldmx4(base + 16384 + bOff[h][ntp], bh);
                ldmx4(base + 24576 + bOff[h][ntp], bl);
                // term-major: 4 distinct accumulators per term group
                mma16816(acc[0][2*ntp],   ah[0], bh[0], bh[1]);
                mma16816(acc[0][2*ntp+1], ah[0], bh[2], bh[3]);
                mma16816(acc[1][2*ntp],   ah[1], bh[0], bh[1]);
                mma16816(acc[1][2*ntp+1], ah[1], bh[2], bh[3]);
                mma16816(acc[0][2*ntp],   ah[0], bl[0], bl[1]);
                mma16816(acc[0][2*ntp+1], ah[0], bl[2], bl[3]);
                mma16816(acc[1][2*ntp],   ah[1], bl[0], bl[1]);
                mma16816(acc[1][2*ntp+1], ah[1], bl[2], bl[3]);
                mma16816(acc[0][2*ntp],   al[0], bh[0], bh[1]);
                mma16816(acc[0][2*ntp+1], al[0], bh[2], bh[3]);
                mma16816(acc[1][2*ntp],   al[1], bh[0], bh[1]);
                mma16816(acc[1][2*ntp+1], al[1], bh[2], bh[3]);
            }
        }
    }

    // ---------------- epilogue ---------------------------------------------
    const int g = lane >> 2, tig = lane & 3;
    const int nBase = n0 + cg * 64;

    float bcol[8][2];
    #pragma unroll
    for (int nt = 0; nt < 8; nt++) {
        bcol[nt][0] = bias[nBase + nt * 8 + tig * 2];
        bcol[nt][1] = bias[nBase + nt * 8 + tig * 2 + 1];
    }

    if (EPI == 0) {
        int part = nBase >> 10;
        int hd   = (nBase & 1023) >> 6;
        #pragma unroll
        for (int mt = 0; mt < 2; mt++)
            #pragma unroll
            for (int half = 0; half < 2; half++) {
                int m = m0 + wm * 32 + mt * 16 + g + half * 8;
                int b = m >> 11, sq = m & 2047;
                size_t rb = (((size_t)b * NH + hd) * NS + sq) * NDH;
                if (part < 2) {
                    float* dst = part ? g_K : g_Q;
                    #pragma unroll
                    for (int nt = 0; nt < 8; nt++) {
                        int d = nt * 8 + tig * 2;
                        float2 v;
                        v.x = acc[mt][nt][half*2]   + bcol[nt][0];
                        v.y = acc[mt][nt][half*2+1] + bcol[nt][1];
                        *(float2*)(dst + rb + d) = v;
                    }
                } else {
                    #pragma unroll
                    for (int nt = 0; nt < 8; nt++) {
                        int d = nt * 8 + tig * 2;
                        float vx = acc[mt][nt][half*2]   + bcol[nt][0];
                        float vy = acc[mt][nt][half*2+1] + bcol[nt][1];
                        uint32_t hi, lo;
                        split2(vx, vy, hi, lo);
                        *(uint32_t*)((char*)g_Vh + (rb + d) * 2) = hi;
                        *(uint32_t*)((char*)g_Vl + (rb + d) * 2) = lo;
                    }
                }
            }
    } else {
        #pragma unroll
        for (int mt = 0; mt < 2; mt++)
            #pragma unroll
            for (int half = 0; half < 2; half++) {
                int m = m0 + wm * 32 + mt * 16 + g + half * 8;
                #pragma unroll
                for (int nt = 0; nt < 8; nt++) {
                    int n = nBase + nt * 8 + tig * 2;
                    float2 v;
                    v.x = acc[mt][nt][half*2]   + bcol[nt][0];
                    v.y = acc[mt][nt][half*2+1] + bcol[nt][1];
                    *(float2*)(C + (size_t)m * N + n) = v;
                }
            }
    }
}

// ===========================================================================
// RoPE: read fp32 Q/K, rotate, write bf16 hi/lo (Q pre-scaled by 0.125).
// ===========================================================================
__global__ void rope_split(const int* __restrict__ p)
{
    int idx = blockIdx.x * blockDim.x + threadIdx.x;
    if (idx >= NB*NH*NS*32) return;
    int i = idx & 31;
    int t = idx >> 5;
    int s = t & (NS - 1);
    int b = t >> 15;
    int pos = p[b * NS + s];

    float f = (float)exp(-(double)i * (9.210340371976184 / 32.0));
    float ang = (float)pos * f;
    float c, sn;
    sincosf(ang, &sn, &c);

    size_t base = (size_t)t * NDH;
    float q1 = g_Q[base + i], q2 = g_Q[base + i + 32];
    float rq1 = (q1 * c + q2 * sn) * 0.125f;
    float rq2 = (q2 * c - q1 * sn) * 0.125f;
    float k1 = g_K[base + i], k2 = g_K[base + i + 32];
    float rk1 = k1 * c + k2 * sn;
    float rk2 = k2 * c - k1 * sn;

    __nv_bfloat16 h;
    h = __float2bfloat16_rn(rq1);
    g_Qh[base + i] = h;      g_Ql[base + i]      = __float2bfloat16_rn(rq1 - __bfloat162float(h));
    h = __float2bfloat16_rn(rq2);
    g_Qh[base + i + 32] = h; g_Ql[base + i + 32] = __float2bfloat16_rn(rq2 - __bfloat162float(h));
    h = __float2bfloat16_rn(rk1);
    g_Kh[base + i] = h;      g_Kl[base + i]      = __float2bfloat16_rn(rk1 - __bfloat162float(h));
    h = __float2bfloat16_rn(rk2);
    g_Kh[base + i + 32] = h; g_Kl[base + i + 32] = __float2bfloat16_rn(rk2 - __bfloat162float(h));
}

// ===========================================================================
// Tensor-core flash attention, pre-split bf16 operands, cp.async K/V stages.
// ===========================================================================
#define AQ_H 0
#define AQ_L 16384
#define ASTG_BASE 32768
#define ASTG 32768
#define AT_SMEM (ASTG_BASE + 2*ASTG)    // 98304

__global__ __launch_bounds__(128, 2) void attn_mma()
{
    extern __shared__ char sma[];
    const uint32_t sb = smem_u32(sma);

    const int tid = threadIdx.x;
    const int warp = tid >> 5, lane = tid & 31;
    const int qt = blockIdx.x, bh = blockIdx.y;

    const size_t qbase  = ((size_t)bh * NS + qt * 128) * NDH;
    const size_t kvbase = (size_t)bh * NS * NDH;

    {
        #pragma unroll
        for (int j = 0; j < 8; j++) {
            int idx = tid + j * 128;
            int row = idx >> 3, c = idx & 7;
            uint32_t o = swz128(row, c);
            size_t go = qbase + (size_t)row * NDH + c * 8;
            cpa16(sb + AQ_H + o, g_Qh + go);
            cpa16(sb + AQ_L + o, g_Ql + go);
        }
        CP_COMMIT();
    }

    const int rKV = tid >> 3, cKV = tid & 7;
    auto issue_kv = [&](int kt) {
        const uint32_t base = sb + ASTG_BASE + (kt & 1) * ASTG;
        #pragma unroll
        for (int j = 0; j < 4; j++) {
            int row = rKV + j * 16;
            uint32_t o = swz128(row, cKV);
            size_t go = kvbase + (size_t)(kt * 64 + row) * NDH + cKV * 8;
            cpa16(base + o,         g_Kh + go);
            cpa16(base + 8192  + o, g_Kl + go);
            cpa16(base + 16384 + o, g_Vh + go);
            cpa16(base + 24576 + o, g_Vl + go);
        }
    };
    issue_kv(0); CP_COMMIT();

    uint32_t qOff[4][2];
    #pragma unroll
    for (int kc = 0; kc < 4; kc++)
        #pragma unroll
        for (int mt = 0; mt < 2; mt++) {
            int r = warp * 32 + mt * 16 + (lane & 15);
            int c = kc * 2 + ((lane >> 4) & 1);
            qOff[kc][mt] = swz128(r, c);
        }
    uint32_t kOff[4][4];
    #pragma unroll
    for (int kc = 0; kc < 4; kc++)
        #pragma unroll
        for (int ntp = 0; ntp < 4; ntp++) {
            int r = ntp * 16 + (lane & 7) + ((lane >> 4) & 1) * 8;
            int c = kc * 2 + ((lane >> 3) & 1);
            kOff[kc][ntp] = swz128(r, c);
        }
    uint32_t vOff[4][4];
    #pragma unroll
    for (int kq = 0; kq < 4; kq++)
        #pragma unroll
        for (int dp = 0; dp < 4; dp++) {
            int r = kq * 16 + (lane & 7) + ((lane >> 3) & 1) * 8;
            int c = dp * 2 + ((lane >> 4) & 1);
            vOff[kq][dp] = swz128(r, c);
        }

    float Oa[2][8][4];
    float mrun[2][2], lrun[2][2];
    #pragma unroll
    for (int mt = 0; mt < 2; mt++) {
        mrun[mt][0] = -INFINITY; mrun[mt][1] = -INFINITY;
        lrun[mt][0] = 0.f;       lrun[mt][1] = 0.f;
        #pragma unroll
        for (int dt = 0; dt < 8; dt++)
            #pragma unroll
            for (int i = 0; i < 4; i++) Oa[mt][dt][i] = 0.f;
    }

    for (int kt = 0; kt < NS / 64; kt++) {
        CP_WAIT(0);
        __syncthreads();
        if (kt + 1 < NS / 64) issue_kv(kt + 1);
        CP_COMMIT();

        const uint32_t kb = sb + ASTG_BASE + (kt & 1) * ASTG;

        float S[2][8][4];
        #pragma unroll
        for (int mt = 0; mt < 2; mt++)
            #pragma unroll
            for (int nt = 0; nt < 8; nt++)
                #pragma unroll
                for (int i = 0; i < 4; i++) S[mt][nt][i] = 0.f;

        #pragma unroll
        for (int kc = 0; kc < 4; kc++) {
            uint32_t qh[2][4], ql[2][4];
            #pragma unroll
            for (int mt = 0; mt < 2; mt++) {
                ldmx4(sb + AQ_H + qOff[kc][mt], qh[mt]);
                ldmx4(sb + AQ_L + qOff[kc][mt], ql[mt]);
            }
            #pragma unroll
            for (int ntp = 0; ntp < 4; ntp++) {
                uint32_t kh[4], kl[4];
                ldmx4(kb + kOff[kc][ntp], kh);
                ldmx4(kb + 8192 + kOff[kc][ntp], kl);
                mma16816(S[0][2*ntp],   qh[0], kh[0], kh[1]);
                mma16816(S[0][2*ntp+1], qh[0], kh[2], kh[3]);
                mma16816(S[1][2*ntp],   qh[1], kh[0], kh[1]);
                mma16816(S[1][2*ntp+1], qh[1], kh[2], kh[3]);
                mma16816(S[0][2*ntp],   qh[0], kl[0], kl[1]);
                mma16816(S[0][2*ntp+1], qh[0], kl[2], kl[3]);
                mma16816(S[1][2*ntp],   qh[1], kl[0], kl[1]);
                mma16816(S[1][2*ntp+1], qh[1], kl[2], kl[3]);
                mma16816(S[0][2*ntp],   ql[0], kh[0], kh[1]);
                mma16816(S[0][2*ntp+1], ql[0], kh[2], kh[3]);
                mma16816(S[1][2*ntp],   ql[1], kh[0], kh[1]);
                mma16816(S[1][2*ntp+1], ql[1], kh[2], kh[3]);
            }
        }

        // ---- online softmax -----------------------------------------------
        #pragma unroll
        for (int mt = 0; mt < 2; mt++) {
            float mx0 = -INFINITY, mx1 = -INFINITY;
            #pragma unroll
            for (int j = 0; j < 8; j++) {
                mx0 = fmaxf(mx0, fmaxf(S[mt][j][0], S[mt][j][1]));
                mx1 = fmaxf(mx1, fmaxf(S[mt][j][2], S[mt][j][3]));
            }
            mx0 = fmaxf(mx0, __shfl_xor_sync(0xffffffffu, mx0, 1));
            mx0 = fmaxf(mx0, __shfl_xor_sync(0xffffffffu, mx0, 2));
            mx1 = fmaxf(mx1, __shfl_xor_sync(0xffffffffu, mx1, 1));
            mx1 = fmaxf(mx1, __shfl_xor_sync(0xffffffffu, mx1, 2));
            float nm0 = fmaxf(mrun[mt][0], mx0);
            float nm1 = fmaxf(mrun[mt][1], mx1);
            float a0 = __expf(mrun[mt][0] - nm0);
            float a1 = __expf(mrun[mt][1] - nm1);
            mrun[mt][0] = nm0; mrun[mt][1] = nm1;
            float s0 = 0.f, s1 = 0.f;
            #pragma unroll
            for (int j = 0; j < 8; j++) {
                S[mt][j][0] = __expf(S[mt][j][0] - nm0); s0 += S[mt][j][0];
                S[mt][j][1] = __expf(S[mt][j][1] - nm0); s0 += S[mt][j][1];
                S[mt][j][2] = __expf(S[mt][j][2] - nm1); s1 += S[mt][j][2];
                S[mt][j][3] = __expf(S[mt][j][3] - nm1); s1 += S[mt][j][3];
            }
            s0 += __shfl_xor_sync(0xffffffffu, s0, 1);
            s0 += __shfl_xor_sync(0xffffffffu, s0, 2);
            s1 += __shfl_xor_sync(0xffffffffu, s1, 1);
            s1 += __shfl_xor_sync(0xffffffffu, s1, 2);
            lrun[mt][0] = lrun[mt][0] * a0 + s0;
            lrun[mt][1] = lrun[mt][1] * a1 + s1;
            #pragma unroll
            for (int dt = 0; dt < 8; dt++) {
                Oa[mt][dt][0] *= a0; Oa[mt][dt][1] *= a0;
                Oa[mt][dt][2] *= a1; Oa[mt][dt][3] *= a1;
            }
        }

        // ---- O += P V (3-term, term-major order) --------------------------
        #pragma unroll
        for (int kq = 0; kq < 4; kq++) {
            uint32_t pah[2][4], pal[2][4];
            #pragma unroll
            for (int mt = 0; mt < 2; mt++) {
                split2(S[mt][2*kq][0],   S[mt][2*kq][1],   pah[mt][0], pal[mt][0]);
                split2(S[mt][2*kq][2],   S[mt][2*kq][3],   pah[mt][1], pal[mt][1]);
                split2(S[mt][2*kq+1][0], S[mt][2*kq+1][1], pah[mt][2], pal[mt][2]);
                split2(S[mt][2*kq+1][2], S[mt][2*kq+1][3], pah[mt][3], pal[mt][3]);
            }
            #pragma unroll
            for (int dp = 0; dp < 4; dp++) {
                uint32_t vh[4], vl[4];
                ldmx4t(kb + 16384 + vOff[kq][dp], vh);
                ldmx4t(kb + 24576 + vOff[kq][dp], vl);
                mma16816(Oa[0][2*dp],   pah[0], vh[0], vh[1]);
                mma16816(Oa[0][2*dp+1], pah[0], vh[2], vh[3]);
                mma16816(Oa[1][2*dp],   pah[1], vh[0], vh[1]);
                mma16816(Oa[1][2*dp+1], pah[1], vh[2], vh[3]);
                mma16816(Oa[0][2*dp],   pah[0], vl[0], vl[1]);
                mma16816(Oa[0][2*dp+1], pah[0], vl[2], vl[3]);
                mma16816(Oa[1][2*dp],   pah[1], vl[0], vl[1]);
                mma16816(Oa[1][2*dp+1], pah[1], vl[2], vl[3]);
                mma16816(Oa[0][2*dp],   pal[0], vh[0], vh[1]);
                mma16816(Oa[0][2*dp+1], pal[0], vh[2], vh[3]);
                mma16816(Oa[1][2*dp],   pal[1], vh[0], vh[1]);
                mma16816(Oa[1][2*dp+1], pal[1], vh[2], vh[3]);
            }
        }
    }

    // ---- epilogue: O /= l -> ctx hi/lo bf16 [B,S,H*Dh] --------------------
    const int b = bh >> 4, h = bh & 15;
    const int g = lane >> 2, tg = lane & 3;
    #pragma unroll
    for (int mt = 0; mt < 2; mt++)
        #pragma unroll
        for (int half = 0; half < 2; half++) {
            int q = qt * 128 + warp * 32 + mt * 16 + g + half * 8;
            float inv = 1.0f / lrun[mt][half];
            size_t rb = ((size_t)b * NS + q) * ND + h * NDH;
            #pragma unroll
            for (int dt = 0; dt < 8; dt++) {
                float vx = Oa[mt][dt][half*2]   * inv;
                float vy = Oa[mt][dt][half*2+1] * inv;
                uint32_t hi, lo;
                split2(vx, vy, hi, lo);
                size_t o = rb + dt * 8 + tg * 2;
                *(uint32_t*)((char*)g_ctxh + o * 2) = hi;
                *(uint32_t*)((char*)g_ctxl + o * 2) = lo;
            }
        }
}

// ===========================================================================
extern "C" void kernel_launch(void* const* d_in, const int* in_sizes, int n_in,
                              void* d_out, int out_size)
{
    (void)in_sizes; (void)n_in; (void)out_size;
    const float* x      = (const float*)d_in[0];
    const int*   p      = (const int*)d_in[1];
    const float* Wqkv_w = (const float*)d_in[2];
    const float* Wqkv_b = (const float*)d_in[3];
    const float* Wo_w   = (const float*)d_in[4];
    const float* Wo_b   = (const float*)d_in[5];
    float* out = (float*)d_out;

    cudaFuncSetAttribute(gemm_bf16<0>,
                         cudaFuncAttributeMaxDynamicSharedMemorySize, GK_SMEM);
    cudaFuncSetAttribute(gemm_bf16<1>,
                         cudaFuncAttributeMaxDynamicSharedMemorySize, GK_SMEM);
    cudaFuncSetAttribute(attn_mma,
                         cudaFuncAttributeMaxDynamicSharedMemorySize, AT_SMEM);

    __nv_bfloat16 *xh, *xl, *wqh, *wql, *woh, *wol, *ctxh, *ctxl;
    cudaGetSymbolAddress((void**)&xh,  g_xh);  cudaGetSymbolAddress((void**)&xl,  g_xl);
    cudaGetSymbolAddress((void**)&wqh, g_wqh); cudaGetSymbolAddress((void**)&wql, g_wql);
    cudaGetSymbolAddress((void**)&woh, g_woh); cudaGetSymbolAddress((void**)&wol, g_wol);
    cudaGetSymbolAddress((void**)&ctxh, g_ctxh); cudaGetSymbolAddress((void**)&ctxl, g_ctxl);

    int n4x = MT * ND / 4, n4wq = 3 * ND * ND / 4, n4wo = ND * ND / 4;
    conv_split<<<(n4x  + 255) / 256, 256>>>((const float4*)x,      (uint2*)xh,  (uint2*)xl,  n4x);
    conv_split<<<(n4wq + 255) / 256, 256>>>((const float4*)Wqkv_w, (uint2*)wqh, (uint2*)wql, n4wq);
    conv_split<<<(n4wo + 255) / 256, 256>>>((const float4*)Wo_w,   (uint2*)woh, (uint2*)wol, n4wo);

    dim3 g1(3 * ND / 128, MT / 128);
    gemm_bf16<0><<<g1, 256, GK_SMEM>>>(xh, xl, wqh, wql, Wqkv_b, nullptr, 3 * ND, ND);

    int nrope = NB * NH * NS * 32;
    rope_split<<<(nrope + 255) / 256, 256>>>(p);

    attn_mma<<<dim3(NS / 128, NB * NH), 128, AT_SMEM>>>();

    dim3 g2(ND / 128, MT / 128);
    gemm_bf16<1><<<g2, 256, GK_SMEM>>>(ctxh, ctxl, woh, wol, Wo_b, out, ND, ND);
}